// round 4
// baseline (speedup 1.0000x reference)
#include <cuda_runtime.h>
#include <cuda_bf16.h>

#define BN 256
#define TN 2048
#define HN 64
#define GN 192   /* 3*H */
#define MB 4     /* batches per scan block */

// ---------------------------------------------------------------------------
// Scratch (no allocation allowed -> __device__ globals)
// ---------------------------------------------------------------------------
__device__ float g_gx[2][(size_t)BN * TN * GN];        // per-direction input gates (reused by both layers)
__device__ float g_out0[(size_t)BN * TN * 2 * HN];     // layer-0 bidirectional output [B*T, 128]
__device__ float g_emb[BN * 2 * HN];                   // layer-1 final states [B, 128]

__device__ __forceinline__ float sigf(float x) {
    return __fdividef(1.f, 1.f + __expf(-x));
}
__device__ __forceinline__ float tanhfast(float x) {
    x = fminf(fmaxf(x, -15.f), 15.f);
    float e = __expf(-2.f * x);
    return __fdividef(1.f - e, 1.f + e);
}

// ---------------------------------------------------------------------------
// Input-gate GEMM: gx[row, g] = bih[g] + sum_i in[row, i] * Wih[g, i]
// rows = B*T flattened (b*T + t), both directions via blockIdx.y.
// 64 rows per block, 192 threads (one gate each), K chunked by 32 through smem.
// ---------------------------------------------------------------------------
__global__ __launch_bounds__(192) void gx_kernel(
    const float* __restrict__ xin, int IN, int use_out0,
    const float* __restrict__ Wf, const float* __restrict__ bf,
    const float* __restrict__ Wb, const float* __restrict__ bb)
{
    const int dir = blockIdx.y;
    const float* __restrict__ W    = dir ? Wb : Wf;
    const float* __restrict__ bias = dir ? bb : bf;
    const float* __restrict__ in   = use_out0 ? g_out0 : xin;
    float* __restrict__ gx = g_gx[dir];
    const int tid = threadIdx.x;
    const long rowbase = (long)blockIdx.x * 64;

    __shared__ float Wsh[32 * 193];   // [i][g], padded rows to kill bank conflicts
    __shared__ float xsh[32 * 68];    // [i][r], padded, float4-aligned reads over r

    float acc[64];
#pragma unroll
    for (int r = 0; r < 64; r++) acc[r] = 0.f;

    for (int kc = 0; kc < IN; kc += 32) {
        const int kw = min(32, IN - kc);
        // stage W chunk (coalesced over i within each gate row)
        for (int idx = tid; idx < kw * 192; idx += 192) {
            int g = idx / kw, i = idx - g * kw;
            Wsh[i * 193 + g] = W[(long)g * IN + kc + i];
        }
        // stage x chunk transposed (coalesced over i within each row)
        for (int idx = tid; idx < kw * 64; idx += 192) {
            int r = idx / kw, i = idx - r * kw;
            xsh[i * 68 + r] = in[(rowbase + r) * IN + kc + i];
        }
        __syncthreads();
        for (int i = 0; i < kw; i++) {
            float wv = Wsh[i * 193 + tid];
            const float4* x4 = (const float4*)&xsh[i * 68];
#pragma unroll
            for (int rv = 0; rv < 16; rv++) {
                float4 xv = x4[rv];
                acc[4 * rv + 0] += wv * xv.x;
                acc[4 * rv + 1] += wv * xv.y;
                acc[4 * rv + 2] += wv * xv.z;
                acc[4 * rv + 3] += wv * xv.w;
            }
        }
        __syncthreads();
    }
    const float bv = bias[tid];
#pragma unroll 4
    for (int r = 0; r < 64; r++)
        gx[(rowbase + r) * GN + tid] = acc[r] + bv;
}

// ---------------------------------------------------------------------------
// Recurrent scan. One thread per gate (192 threads), MB batches per block.
// Whh row lives in registers (16 x float4). h in smem (float4, broadcast reads).
// layer 0: writes full sequence into g_out0 (fwd -> [0:64], bwd -> [64:128],
//          backward steps land at original time index T-1-s).
// layer 1: writes only final states into g_emb.
// ---------------------------------------------------------------------------
__global__ __launch_bounds__(192) void scan_kernel(
    int layer,
    const float* __restrict__ Whh_f, const float* __restrict__ bhh_f,
    const float* __restrict__ Whh_b, const float* __restrict__ bhh_b)
{
    const int dir = blockIdx.y;
    const int tid = threadIdx.x;                 // gate id 0..191
    const float* __restrict__ Whh = dir ? Whh_b : Whh_f;
    const float bh = (dir ? bhh_b : bhh_f)[tid];
    const float* __restrict__ gx = g_gx[dir];
    const int bbase = blockIdx.x * MB;
    const int dirOff = dir ? HN : 0;

    __shared__ float4 h4[MB * 16];               // h state, [b][jv] float4
    __shared__ float gh_s[MB][GN];               // hidden-gate pre-activations
    __shared__ float sx_s[MB][GN];               // input-gate values
    float* hsh = (float*)h4;

    // Whh row -> registers
    float4 w[16];
    const float4* Wsrc = (const float4*)Whh;
#pragma unroll
    for (int jv = 0; jv < 16; jv++) w[jv] = Wsrc[tid * 16 + jv];

    for (int idx = tid; idx < MB * 16; idx += 192) h4[idx] = make_float4(0.f, 0.f, 0.f, 0.f);
    __syncthreads();

    // walking gx pointers per batch lane
    const float* gp[MB];
    const long stepoff = dir ? -(long)GN : (long)GN;
    const long t0 = dir ? (TN - 1) : 0;
#pragma unroll
    for (int b = 0; b < MB; b++)
        gp[b] = gx + ((long)(bbase + b) * TN + t0) * GN + tid;

    float* seq = (layer == 0) ? g_out0 : nullptr;

    for (int s = 0; s < TN; ++s) {
        const int t = dir ? (TN - 1 - s) : s;
        float xg[MB];
#pragma unroll
        for (int b = 0; b < MB; b++) { xg[b] = __ldg(gp[b]); gp[b] += stepoff; }
        float acc[MB];
#pragma unroll
        for (int b = 0; b < MB; b++) acc[b] = bh;
#pragma unroll
        for (int jv = 0; jv < 16; jv++) {
            const float4 wv = w[jv];
#pragma unroll
            for (int b = 0; b < MB; b++) {
                const float4 hv = h4[b * 16 + jv];
                acc[b] += wv.x * hv.x;
                acc[b] += wv.y * hv.y;
                acc[b] += wv.z * hv.z;
                acc[b] += wv.w * hv.w;
            }
        }
#pragma unroll
        for (int b = 0; b < MB; b++) { gh_s[b][tid] = acc[b]; sx_s[b][tid] = xg[b]; }
        __syncthreads();
        for (int idx = tid; idx < MB * HN; idx += 192) {
            const int b = idx >> 6, hu = idx & 63;
            const float r = sigf(sx_s[b][hu]       + gh_s[b][hu]);
            const float z = sigf(sx_s[b][64 + hu]  + gh_s[b][64 + hu]);
            const float n = tanhfast(sx_s[b][128 + hu] + r * gh_s[b][128 + hu]);
            const float hold = hsh[b * 64 + hu];
            const float hnew = n + z * (hold - n);
            hsh[b * 64 + hu] = hnew;
            if (seq)
                seq[((long)(bbase + b) * TN + t) * (2 * HN) + dirOff + hu] = hnew;
        }
        __syncthreads();
    }

    if (layer == 1) {
        for (int idx = tid; idx < MB * HN; idx += 192) {
            const int b = idx >> 6, hu = idx & 63;
            g_emb[(bbase + b) * (2 * HN) + dirOff + hu] = hsh[b * 64 + hu];
        }
    }
}

// ---------------------------------------------------------------------------
// Head: LayerNorm(128) -> ReLU(W1) -> W2. One block per batch row.
// ---------------------------------------------------------------------------
__global__ __launch_bounds__(128) void head_kernel(
    const float* __restrict__ ln_g, const float* __restrict__ ln_b,
    const float* __restrict__ W1, const float* __restrict__ b1,
    const float* __restrict__ W2, const float* __restrict__ b2,
    float* __restrict__ out)
{
    const int b = blockIdx.x, tid = threadIdx.x;
    __shared__ float ysh[128], hsh[64], red[8];

    const float e = g_emb[b * 128 + tid];
    float s = e, q = e * e;
#pragma unroll
    for (int o = 16; o > 0; o >>= 1) {
        s += __shfl_down_sync(~0u, s, o);
        q += __shfl_down_sync(~0u, q, o);
    }
    if ((tid & 31) == 0) { red[tid >> 5] = s; red[4 + (tid >> 5)] = q; }
    __syncthreads();
    const float ssum = red[0] + red[1] + red[2] + red[3];
    const float qsum = red[4] + red[5] + red[6] + red[7];
    const float mu = ssum * (1.f / 128.f);
    const float var = qsum * (1.f / 128.f) - mu * mu;
    ysh[tid] = (e - mu) * rsqrtf(var + 1e-5f) * ln_g[tid] + ln_b[tid];
    __syncthreads();
    if (tid < 64) {
        float a = b1[tid];
#pragma unroll 8
        for (int i = 0; i < 128; i++) a += ysh[i] * W1[tid * 128 + i];
        hsh[tid] = fmaxf(a, 0.f);
    }
    __syncthreads();
    if (tid < 11) {
        float a = b2[tid];
#pragma unroll
        for (int i = 0; i < 64; i++) a += hsh[i] * W2[tid * 64 + i];
        out[b * 11 + tid] = a;
    }
}

// ---------------------------------------------------------------------------
extern "C" void kernel_launch(void* const* d_in, const int* in_sizes, int n_in,
                              void* d_out, int out_size)
{
    const float* x     = (const float*)d_in[0];
    const float* Wih00 = (const float*)d_in[1];
    const float* Whh00 = (const float*)d_in[2];
    const float* bih00 = (const float*)d_in[3];
    const float* bhh00 = (const float*)d_in[4];
    const float* Wih01 = (const float*)d_in[5];
    const float* Whh01 = (const float*)d_in[6];
    const float* bih01 = (const float*)d_in[7];
    const float* bhh01 = (const float*)d_in[8];
    const float* Wih10 = (const float*)d_in[9];
    const float* Whh10 = (const float*)d_in[10];
    const float* bih10 = (const float*)d_in[11];
    const float* bhh10 = (const float*)d_in[12];
    const float* Wih11 = (const float*)d_in[13];
    const float* Whh11 = (const float*)d_in[14];
    const float* bih11 = (const float*)d_in[15];
    const float* bhh11 = (const float*)d_in[16];
    const float* ln_g  = (const float*)d_in[17];
    const float* ln_b  = (const float*)d_in[18];
    const float* W1    = (const float*)d_in[19];
    const float* b1    = (const float*)d_in[20];
    const float* W2    = (const float*)d_in[21];
    const float* b2    = (const float*)d_in[22];
    float* out = (float*)d_out;

    const dim3 gxGrid(BN * TN / 64, 2);
    const dim3 scGrid(BN / MB, 2);

    // Layer 0: input gates from x (IN=29), then bidirectional scan -> g_out0
    gx_kernel<<<gxGrid, 192>>>(x, 29, 0, Wih00, bih00, Wih01, bih01);
    scan_kernel<<<scGrid, 192>>>(0, Whh00, bhh00, Whh01, bhh01);

    // Layer 1: input gates from g_out0 (IN=128), then scan -> g_emb (finals only)
    gx_kernel<<<gxGrid, 192>>>(x, 128, 1, Wih10, bih10, Wih11, bih11);
    scan_kernel<<<scGrid, 192>>>(1, Whh10, bhh10, Whh11, bhh11);

    // Head
    head_kernel<<<BN, 128>>>(ln_g, ln_b, W1, b1, W2, b2, out);
}

// round 5
// speedup vs baseline: 1.9245x; 1.9245x over previous
#include <cuda_runtime.h>
#include <cuda_bf16.h>

#define BN 256
#define TN 2048
#define HN 64
#define GN 192   /* 3*H */
#define MB 4     /* batches per scan block */

// ---------------------------------------------------------------------------
// Scratch (no allocation allowed -> __device__ globals)
// NOTE: scan prefetch deliberately over/under-runs one row past its direction
// slab; layout [2][...] keeps those accesses inside this object.
// ---------------------------------------------------------------------------
__device__ float g_gx[2][(size_t)BN * TN * GN];        // per-direction input gates
__device__ float g_out0[(size_t)BN * TN * 2 * HN];     // layer-0 output [B*T, 128]
__device__ float g_emb[BN * 2 * HN];                   // layer-1 final states [B, 128]

__device__ __forceinline__ float sigf(float x) {
    return __fdividef(1.f, 1.f + __expf(-x));
}
__device__ __forceinline__ float tanhfast(float x) {
    x = fminf(fmaxf(x, -15.f), 15.f);
    float e = __expf(-2.f * x);
    return __fdividef(1.f - e, 1.f + e);
}

// Packed fp32x2 helpers (Blackwell dual-rate fp32 path)
#define FFMA2(acc, a, b) \
    asm("fma.rn.f32x2 %0, %1, %2, %0;" : "+l"(acc) : "l"(a), "l"(b))

__device__ __forceinline__ unsigned long long packdup(float v) {
    unsigned long long r;
    asm("mov.b64 %0, {%1, %1};" : "=l"(r) : "f"(v));
    return r;
}
__device__ __forceinline__ float2 unpack2(unsigned long long p) {
    float2 f;
    asm("mov.b64 {%0, %1}, %2;" : "=f"(f.x), "=f"(f.y) : "l"(p));
    return f;
}

// ---------------------------------------------------------------------------
// Input-gate GEMM: gx[row, g] = bih[g] + sum_i in[row, i] * Wih[g, i]
// 64 rows/block, 192 threads (one gate each), K chunked by 32 via smem.
// IN is a template constant: staging index math becomes shifts, loops unroll.
// Inner loop uses packed f32x2 over row pairs.
// ---------------------------------------------------------------------------
template <int IN>
__global__ __launch_bounds__(192) void gx_kernel(
    const float* __restrict__ xin, int use_out0,
    const float* __restrict__ Wf, const float* __restrict__ bf,
    const float* __restrict__ Wb, const float* __restrict__ bb)
{
    const int dir = blockIdx.y;
    const float* __restrict__ W    = dir ? Wb : Wf;
    const float* __restrict__ bias = dir ? bb : bf;
    const float* __restrict__ in   = use_out0 ? g_out0 : xin;
    float* __restrict__ gx = g_gx[dir];
    const int tid = threadIdx.x;
    const long rowbase = (long)blockIdx.x * 64;

    __shared__ float Wsh[32 * 193];   // [i][g]
    __shared__ float xsh[32 * 68];    // [i][r], 16B-aligned rows (272B stride)

    unsigned long long acc2[32];      // 32 packed pairs = 64 row accumulators
#pragma unroll
    for (int rv = 0; rv < 32; rv++) acc2[rv] = 0ull;   // bits of (0.f,0.f)

#pragma unroll
    for (int kc = 0; kc < IN; kc += 32) {
        const int kw = (IN - kc < 32) ? (IN - kc) : 32;   // compile-time per kc
        // stage W chunk (coalesced over i within each gate row)
        for (int idx = tid; idx < kw * 192; idx += 192) {
            int g = idx / kw, i = idx - g * kw;
            Wsh[i * 193 + g] = W[(long)g * IN + kc + i];
        }
        // stage x chunk transposed
        for (int idx = tid; idx < kw * 64; idx += 192) {
            int r = idx / kw, i = idx - r * kw;
            xsh[i * 68 + r] = in[(rowbase + r) * IN + kc + i];
        }
        __syncthreads();
        for (int i = 0; i < kw; i++) {
            const unsigned long long w2 = packdup(Wsh[i * 193 + tid]);
            const ulonglong2* x2 = (const ulonglong2*)&xsh[i * 68];
#pragma unroll
            for (int rv = 0; rv < 16; rv++) {
                ulonglong2 xv = x2[rv];
                FFMA2(acc2[2 * rv + 0], w2, xv.x);
                FFMA2(acc2[2 * rv + 1], w2, xv.y);
            }
        }
        __syncthreads();
    }
    const float bv = bias[tid];
#pragma unroll 8
    for (int rv = 0; rv < 32; rv++) {
        float2 p = unpack2(acc2[rv]);
        gx[(rowbase + 2 * rv + 0) * GN + tid] = p.x + bv;
        gx[(rowbase + 2 * rv + 1) * GN + tid] = p.y + bv;
    }
}

// ---------------------------------------------------------------------------
// Recurrent scan. 192 threads (one per gate), MB=4 batches per block.
// Whh row pre-duplicated into 64 packed f32x2 registers. h kept in smem as
// float4 h[j] = (b0,b1,b2,b3) so one LDS.128 feeds two FFMA2.
// gx loads are prefetched one full step ahead (register double buffer).
// ---------------------------------------------------------------------------
__global__ __launch_bounds__(192) void scan_kernel(
    int layer,
    const float* __restrict__ Whh_f, const float* __restrict__ bhh_f,
    const float* __restrict__ Whh_b, const float* __restrict__ bhh_b)
{
    const int dir = blockIdx.x & 1;
    const int blk = blockIdx.x >> 1;
    const int tid = threadIdx.x;                 // gate id 0..191
    const float* __restrict__ Whh = dir ? Whh_b : Whh_f;
    const float bh = (dir ? bhh_b : bhh_f)[tid];
    const float* __restrict__ gx = g_gx[dir];
    const int bbase = blk * MB;
    const int dirOff = dir ? HN : 0;

    __shared__ float4 hsh4[HN];      // h[j] = (b0,b1,b2,b3)
    __shared__ float4 gh4[GN];       // hidden-gate pre-activations, per-gate 4 batches
    __shared__ float4 sx4[GN];       // input-gate values

    // Whh row -> packed duplicated registers (128 regs; 1 block/SM, fine)
    unsigned long long w2[HN];
#pragma unroll
    for (int j = 0; j < HN; j++) w2[j] = packdup(Whh[tid * HN + j]);
    const unsigned long long bh2 = packdup(bh);

    if (tid < HN) hsh4[tid] = make_float4(0.f, 0.f, 0.f, 0.f);
    __syncthreads();

    // walking gx pointers per batch lane
    const float* gp[MB];
    const long stepoff = dir ? -(long)GN : (long)GN;
    const long t0 = dir ? (TN - 1) : 0;
#pragma unroll
    for (int b = 0; b < MB; b++)
        gp[b] = gx + ((long)(bbase + b) * TN + t0) * GN + tid;

    // preload step 0
    float xg[MB];
#pragma unroll
    for (int b = 0; b < MB; b++) { xg[b] = __ldg(gp[b]); gp[b] += stepoff; }

    float* __restrict__ seq = (layer == 0) ? g_out0 : nullptr;

    for (int s = 0; s < TN; ++s) {
        const int t = dir ? (TN - 1 - s) : s;

        // prefetch step s+1 (pointer runs one row past the slab on the last
        // step; lands inside the adjacent g_gx direction slab -> in bounds)
        float xgn[MB];
#pragma unroll
        for (int b = 0; b < MB; b++) { xgn[b] = __ldg(gp[b]); gp[b] += stepoff; }

        unsigned long long acc01 = bh2, acc23 = bh2;
        const ulonglong2* h2 = (const ulonglong2*)hsh4;
#pragma unroll
        for (int j = 0; j < HN; j++) {
            ulonglong2 hv = h2[j];              // one LDS.128, broadcast
            FFMA2(acc01, w2[j], hv.x);
            FFMA2(acc23, w2[j], hv.y);
        }
        {
            float2 lo = unpack2(acc01), hi = unpack2(acc23);
            gh4[tid] = make_float4(lo.x, lo.y, hi.x, hi.y);
            sx4[tid] = make_float4(xg[0], xg[1], xg[2], xg[3]);
        }
#pragma unroll
        for (int b = 0; b < MB; b++) xg[b] = xgn[b];
        __syncthreads();

        // pointwise: item = hu*4 + b (conflict-free smem access pattern)
        const float* ghf = (const float*)gh4;
        const float* sxf = (const float*)sx4;
        float* hf = (float*)hsh4;
        for (int item = tid; item < MB * HN; item += 192) {
            const int hu = item >> 2, b = item & 3;
            const float r = sigf(sxf[hu * 4 + b] + ghf[hu * 4 + b]);
            const float z = sigf(sxf[(64 + hu) * 4 + b] + ghf[(64 + hu) * 4 + b]);
            const float n = tanhfast(sxf[(128 + hu) * 4 + b] + r * ghf[(128 + hu) * 4 + b]);
            const float hold = hf[item];
            const float hnew = n + z * (hold - n);
            hf[item] = hnew;
            if (seq)
                seq[((long)(bbase + b) * TN + t) * (2 * HN) + dirOff + hu] = hnew;
        }
        __syncthreads();
    }

    if (layer == 1) {
        const float* hf = (const float*)hsh4;
        for (int item = tid; item < MB * HN; item += 192) {
            const int hu = item >> 2, b = item & 3;
            g_emb[(bbase + b) * (2 * HN) + dirOff + hu] = hf[item];
        }
    }
}

// ---------------------------------------------------------------------------
// Head: LayerNorm(128) -> ReLU(W1) -> W2. One block per batch row.
// ---------------------------------------------------------------------------
__global__ __launch_bounds__(128) void head_kernel(
    const float* __restrict__ ln_g, const float* __restrict__ ln_b,
    const float* __restrict__ W1, const float* __restrict__ b1,
    const float* __restrict__ W2, const float* __restrict__ b2,
    float* __restrict__ out)
{
    const int b = blockIdx.x, tid = threadIdx.x;
    __shared__ float ysh[128], hsh[64], red[8];

    const float e = g_emb[b * 128 + tid];
    float s = e, q = e * e;
#pragma unroll
    for (int o = 16; o > 0; o >>= 1) {
        s += __shfl_down_sync(~0u, s, o);
        q += __shfl_down_sync(~0u, q, o);
    }
    if ((tid & 31) == 0) { red[tid >> 5] = s; red[4 + (tid >> 5)] = q; }
    __syncthreads();
    const float ssum = red[0] + red[1] + red[2] + red[3];
    const float qsum = red[4] + red[5] + red[6] + red[7];
    const float mu = ssum * (1.f / 128.f);
    const float var = qsum * (1.f / 128.f) - mu * mu;
    ysh[tid] = (e - mu) * rsqrtf(var + 1e-5f) * ln_g[tid] + ln_b[tid];
    __syncthreads();
    if (tid < 64) {
        float a = b1[tid];
#pragma unroll 8
        for (int i = 0; i < 128; i++) a += ysh[i] * W1[tid * 128 + i];
        hsh[tid] = fmaxf(a, 0.f);
    }
    __syncthreads();
    if (tid < 11) {
        float a = b2[tid];
#pragma unroll
        for (int i = 0; i < 64; i++) a += hsh[i] * W2[tid * 64 + i];
        out[b * 11 + tid] = a;
    }
}

// ---------------------------------------------------------------------------
extern "C" void kernel_launch(void* const* d_in, const int* in_sizes, int n_in,
                              void* d_out, int out_size)
{
    const float* x     = (const float*)d_in[0];
    const float* Wih00 = (const float*)d_in[1];
    const float* Whh00 = (const float*)d_in[2];
    const float* bih00 = (const float*)d_in[3];
    const float* bhh00 = (const float*)d_in[4];
    const float* Wih01 = (const float*)d_in[5];
    const float* Whh01 = (const float*)d_in[6];
    const float* bih01 = (const float*)d_in[7];
    const float* bhh01 = (const float*)d_in[8];
    const float* Wih10 = (const float*)d_in[9];
    const float* Whh10 = (const float*)d_in[10];
    const float* bih10 = (const float*)d_in[11];
    const float* bhh10 = (const float*)d_in[12];
    const float* Wih11 = (const float*)d_in[13];
    const float* Whh11 = (const float*)d_in[14];
    const float* bih11 = (const float*)d_in[15];
    const float* bhh11 = (const float*)d_in[16];
    const float* ln_g  = (const float*)d_in[17];
    const float* ln_b  = (const float*)d_in[18];
    const float* W1    = (const float*)d_in[19];
    const float* b1    = (const float*)d_in[20];
    const float* W2    = (const float*)d_in[21];
    const float* b2    = (const float*)d_in[22];
    float* out = (float*)d_out;

    const dim3 gxGrid(BN * TN / 64, 2);
    const int scBlocks = (BN / MB) * 2;   // dir folded into blockIdx.x

    // Layer 0: input gates from x (IN=29), then bidirectional scan -> g_out0
    gx_kernel<29><<<gxGrid, 192>>>(x, 0, Wih00, bih00, Wih01, bih01);
    scan_kernel<<<scBlocks, 192>>>(0, Whh00, bhh00, Whh01, bhh01);

    // Layer 1: input gates from g_out0 (IN=128), then scan -> g_emb
    gx_kernel<128><<<gxGrid, 192>>>(x, 1, Wih10, bih10, Wih11, bih11);
    scan_kernel<<<scBlocks, 192>>>(1, Whh10, bhh10, Whh11, bhh11);

    // Head
    head_kernel<<<BN, 128>>>(ln_g, ln_b, W1, b1, W2, b2, out);
}